// round 4
// baseline (speedup 1.0000x reference)
#include <cuda_runtime.h>
#include <math.h>

#define Bn 4
#define Sn 512
#define Hd 128
#define En 32     // embed_dim — E=32 (V,E,H = 128,32,128)
#define Vv 128
#define G4 512    // 4*H

typedef unsigned long long u64;

// ---------------- scratch (device globals: no allocation allowed) ----------------
__device__ float g_xproj[Bn*Sn*G4];   // 4 MB
__device__ float g_out[Bn*Sn*Hd];     // 1 MB
__device__ float g_q[Bn*Sn*Hd];       // 1 MB
__device__ float g_k[Bn*Sn*Hd];       // 1 MB
__device__ float g_scores[Bn*Sn*Sn];  // 4 MB (scores, then softmax weights in-place)
__device__ float g_state_dump[2*Bn*Hd]; // fallback if d_out has no room for hT/cT

// ---------------- helpers ----------------
__device__ __forceinline__ u64 fma2(u64 a, u64 b, u64 c) {
    u64 d;
    asm("fma.rn.f32x2 %0, %1, %2, %3;" : "=l"(d) : "l"(a), "l"(b), "l"(c));
    return d;
}
__device__ __forceinline__ u64 add2(u64 a, u64 b) {
    u64 d;
    asm("add.rn.f32x2 %0, %1, %2;" : "=l"(d) : "l"(a), "l"(b));
    return d;
}
__device__ __forceinline__ float sigf(float x) {
    return 1.0f / (1.0f + expf(-x));
}

// ============================================================================
// Kernel 1: xproj[r, col] = dot(emb[x[r], :32], W_ih[col, :32]) + b_ih + b_hh
// 16 rows/block, 512 threads (one per output column), W_ih row in registers.
// ============================================================================
__global__ void k_embed_xproj(const int* __restrict__ x, const float* __restrict__ emb,
                              const float* __restrict__ Wih, const float* __restrict__ bih,
                              const float* __restrict__ bhh) {
    __shared__ __align__(16) float e_s[16 * En];   // 16 rows x 32
    int tid = threadIdx.x;                          // 512
    int r0 = blockIdx.x * 16;
    // 512 threads load exactly 16*32 = 512 embedding floats
    e_s[tid] = emb[x[r0 + (tid >> 5)] * En + (tid & 31)];
    __syncthreads();

    int col = tid;
    const float4* W4 = (const float4*)(Wih + col * En);
    float4 w[8];
#pragma unroll
    for (int i = 0; i < 8; i++) w[i] = W4[i];
    float bb = bih[col] + bhh[col];

#pragma unroll 4
    for (int r = 0; r < 16; r++) {
        const float4* e4 = (const float4*)(e_s + r * En);
        float a = bb;
#pragma unroll
        for (int i = 0; i < 8; i++) {
            float4 e = e4[i];
            a = fmaf(w[i].x, e.x, a);
            a = fmaf(w[i].y, e.y, a);
            a = fmaf(w[i].z, e.z, a);
            a = fmaf(w[i].w, e.w, a);
        }
        g_xproj[(size_t)(r0 + r) * G4 + col] = a;
    }
}

// ============================================================================
// Kernel 2: LSTM (packed f32x2). One block per batch, 1024 threads.
// Thread t: gate row j = t&511, half = t>>9 (64-wide k-range).
// W_hh split: 40 floats/thread in regs + 24 in smem. fma.rn.f32x2 = 2 MAC/op.
// ============================================================================
#define RKP 20   // register k-pairs (40 floats)
#define SKP 12   // smem k-pairs (24 floats)
#define LSTM_SMEM (2*SKP*512*8 + 1024*4 + 128*4)

__global__ __launch_bounds__(1024, 1) void k_lstm(const float* __restrict__ Whh,
                                                  float* __restrict__ hT,
                                                  float* __restrict__ cT) {
    extern __shared__ __align__(16) char smraw[];
    u64*   WS   = (u64*)smraw;                            // [2*SKP*512]
    float* part = (float*)(smraw + (size_t)2*SKP*512*8);  // [1024]
    float* h_s  = part + 1024;                            // [128]

    int tid  = threadIdx.x;
    int j    = tid & 511;
    int half = tid >> 9;
    int b    = blockIdx.x;

    const u64* W2 = (const u64*)Whh;         // k-pairs; row j = 64 pairs
    int base = j * 64 + half * 32;
    u64 wreg[RKP];
#pragma unroll
    for (int p = 0; p < RKP; p++) wreg[p] = W2[base + p];
#pragma unroll
    for (int p = 0; p < SKP; p++) WS[(half * SKP + p) * 512 + j] = W2[base + RKP + p];
    if (tid < 128) h_s[tid] = 0.0f;
    float c = 0.0f, hlast = 0.0f;
    __syncthreads();

    const u64*   h2   = (const u64*)h_s;
    const float* xpb  = g_xproj + (size_t)b * Sn * G4;
    float*       outb = g_out   + (size_t)b * Sn * Hd;
    int hb = half * 32;

    for (int t = 0; t < Sn; t++) {
        float xp0 = 0.f, xp1 = 0.f, xp2 = 0.f, xp3 = 0.f;
        if (tid < 128) {
            const float* xp = xpb + (size_t)t * G4;
            xp0 = xp[tid];       xp1 = xp[tid + 128];
            xp2 = xp[tid + 256]; xp3 = xp[tid + 384];
        }
        // phase A: partial dot of W_hh[j, half-range] with h
        u64 a[4] = {0ull, 0ull, 0ull, 0ull};
#pragma unroll
        for (int p = 0; p < RKP; p++)
            a[p & 3] = fma2(wreg[p], h2[hb + p], a[p & 3]);
#pragma unroll
        for (int p = 0; p < SKP; p++)
            a[p & 3] = fma2(WS[(half * SKP + p) * 512 + j], h2[hb + RKP + p], a[p & 3]);
        u64 ssum = add2(add2(a[0], a[1]), add2(a[2], a[3]));
        float2 sf = *(float2*)&ssum;
        part[tid] = sf.x + sf.y;
        __syncthreads();

        // phase B: gates + state update (threads 0..127)
        if (tid < 128) {
            float gi = xp0 + part[tid]       + part[512 + tid];
            float gf = xp1 + part[128 + tid] + part[640 + tid];
            float gg = xp2 + part[256 + tid] + part[768 + tid];
            float go = xp3 + part[384 + tid] + part[896 + tid];
            c = sigf(gf) * c + sigf(gi) * tanhf(gg);
            float h = sigf(go) * tanhf(c);
            hlast = h;
            h_s[tid] = h;
            outb[(size_t)t * Hd + tid] = h;
        }
        __syncthreads();
    }
    if (tid < 128) {
        hT[b * Hd + tid] = hlast;
        cT[b * Hd + tid] = c;
    }
}

// ============================================================================
// Kernel 3: q = out @ Wqᵀ + bq ; k = out @ Wkᵀ + bk. 16 rows/block, 256 thr.
// ============================================================================
__global__ void k_qk(const float* __restrict__ Wq, const float* __restrict__ bq,
                     const float* __restrict__ Wk, const float* __restrict__ bk) {
    __shared__ __align__(16) float o_s[16 * 128];
    int tid = threadIdx.x;
    int r0 = blockIdx.x * 16;
    for (int i = tid; i < 2048; i += 256)
        o_s[i] = g_out[(size_t)r0 * Hd + i];
    __syncthreads();

    const float* W    = (tid < 128) ? Wq : Wk;
    const float* bias = (tid < 128) ? bq : bk;
    float*       dst  = (tid < 128) ? g_q : g_k;
    int c = tid & 127;

    const float4* W4  = (const float4*)W;
    const float4* os4 = (const float4*)o_s;
    float acc[16];
    float bb = bias[c];
#pragma unroll
    for (int r = 0; r < 16; r++) acc[r] = bb;
#pragma unroll 4
    for (int k4 = 0; k4 < 32; k4++) {
        float4 w = W4[c * 32 + k4];
#pragma unroll
        for (int r = 0; r < 16; r++) {
            float4 o = os4[r * 32 + k4];
            acc[r] = fmaf(w.x, o.x, acc[r]);
            acc[r] = fmaf(w.y, o.y, acc[r]);
            acc[r] = fmaf(w.z, o.z, acc[r]);
            acc[r] = fmaf(w.w, o.w, acc[r]);
        }
    }
#pragma unroll
    for (int r = 0; r < 16; r++)
        dst[(size_t)(r0 + r) * Hd + c] = acc[r];
}

// ============================================================================
// Kernel 4: scores[b,s,t] = sum_h v[h]*tanh(q[b,s,h]+k[b,t,h]) for t<=s.
// 32x32 (s,t) tiles over the causal triangle.
// ============================================================================
__global__ void k_scores(const float* __restrict__ v) {
    __shared__ __align__(16) float q_s[32 * 128];
    __shared__ float kT[128 * 33];
    __shared__ float v_s[128];
    int tid = threadIdx.x;
    int b = blockIdx.x / 136;
    int r = blockIdx.x % 136;
    int si = 0;
    while (((si + 1) * (si + 2)) >> 1 <= r) si++;
    int ti = r - ((si * (si + 1)) >> 1);
    int s0 = si * 32, t0 = ti * 32;

    const float* qb = g_q + ((size_t)b * Sn + s0) * Hd;
    const float* kb = g_k + ((size_t)b * Sn + t0) * Hd;
    for (int i = tid; i < 4096; i += 256) q_s[i] = qb[i];
    for (int i = tid; i < 4096; i += 256) {
        int tt = i >> 7, h = i & 127;
        kT[h * 33 + tt] = kb[i];
    }
    if (tid < 128) v_s[tid] = v[tid];
    __syncthreads();

    int tl = tid & 31, sb = tid >> 5;
    float acc[4] = {0.f, 0.f, 0.f, 0.f};
#pragma unroll 2
    for (int h = 0; h < 128; h++) {
        float kv = kT[h * 33 + tl];
        float vv = v_s[h];
#pragma unroll
        for (int p = 0; p < 4; p++)
            acc[p] += vv * tanhf(q_s[(sb + (p << 3)) * 128 + h] + kv);
    }
    int t = t0 + tl;
#pragma unroll
    for (int p = 0; p < 4; p++) {
        int s = s0 + sb + (p << 3);
        if (t <= s)
            g_scores[((size_t)b * Sn + s) * Sn + t] = acc[p];
    }
}

// ============================================================================
// Kernel 5: causal softmax per (b,s) row, zero-fills masked entries.
// ============================================================================
__global__ void k_softmax() {
    __shared__ float red[256];
    int tid = threadIdx.x;
    int row = blockIdx.x;
    int s = row & (Sn - 1);
    float* sc = g_scores + (size_t)row * Sn;
    int n = s + 1;

    float x0 = (tid < n) ? sc[tid] : -1e30f;
    float x1 = (tid + 256 < n) ? sc[tid + 256] : -1e30f;
    red[tid] = fmaxf(x0, x1);
    __syncthreads();
    for (int o = 128; o > 0; o >>= 1) {
        if (tid < o) red[tid] = fmaxf(red[tid], red[tid + o]);
        __syncthreads();
    }
    float m = red[0];
    __syncthreads();

    float e0 = (tid < n) ? expf(x0 - m) : 0.0f;
    float e1 = (tid + 256 < n) ? expf(x1 - m) : 0.0f;
    red[tid] = e0 + e1;
    __syncthreads();
    for (int o = 128; o > 0; o >>= 1) {
        if (tid < o) red[tid] += red[tid + o];
        __syncthreads();
    }
    float inv = 1.0f / red[0];
    sc[tid]       = e0 * inv;
    sc[tid + 256] = e1 * inv;
}

// ============================================================================
// Kernel 6: ctx then logits = [out, ctx] @ Wfᵀ + bf. 32 s-rows/block.
// ============================================================================
__global__ void k_ctx_logits(const float* __restrict__ Wf, const float* __restrict__ bf,
                             float* __restrict__ logits) {
    __shared__ float w_s[32 * 32];
    __shared__ __align__(16) float ctx_s[32 * 128];
    __shared__ __align__(16) float out_s[32 * 128];
    int tid = threadIdx.x;
    int b  = blockIdx.x >> 4;
    int s0 = (blockIdx.x & 15) << 5;

    for (int i = tid; i < 4096; i += 256)
        out_s[i] = g_out[((size_t)b * Sn + s0) * Hd + i];

    int h = tid & 127, sg = tid >> 7;
    float acc[16];
#pragma unroll
    for (int i = 0; i < 16; i++) acc[i] = 0.0f;

    int tend = s0 + 32;                  // weights are 0 beyond each row's s
    for (int tc0 = 0; tc0 < tend; tc0 += 32) {
        __syncthreads();
        for (int i = tid; i < 1024; i += 256) {
            int sl = i >> 5, tc = i & 31;
            w_s[i] = g_scores[((size_t)b * Sn + s0 + sl) * Sn + tc0 + tc];
        }
        __syncthreads();
#pragma unroll 4
        for (int tc = 0; tc < 32; tc++) {
            float ov = g_out[((size_t)b * Sn + tc0 + tc) * Hd + h];
#pragma unroll
            for (int i = 0; i < 16; i++)
                acc[i] = fmaf(w_s[(2 * i + sg) * 32 + tc], ov, acc[i]);
        }
    }
    __syncthreads();
#pragma unroll
    for (int i = 0; i < 16; i++) ctx_s[(2 * i + sg) * 128 + h] = acc[i];
    __syncthreads();

    int vc = tid & 127;
    float bb = bf[vc];
    const float4* Wf4 = (const float4*)Wf;
    const float4* os4 = (const float4*)out_s;
    const float4* cs4 = (const float4*)ctx_s;
    float acc2[16];
#pragma unroll
    for (int i = 0; i < 16; i++) acc2[i] = 0.0f;
#pragma unroll 2
    for (int k4 = 0; k4 < 32; k4++) {
        float4 w = Wf4[vc * 64 + k4];
#pragma unroll
        for (int i = 0; i < 16; i++) {
            float4 o = os4[(2 * i + sg) * 32 + k4];
            acc2[i] = fmaf(w.x, o.x, acc2[i]);
            acc2[i] = fmaf(w.y, o.y, acc2[i]);
            acc2[i] = fmaf(w.z, o.z, acc2[i]);
            acc2[i] = fmaf(w.w, o.w, acc2[i]);
        }
    }
#pragma unroll 2
    for (int k4 = 0; k4 < 32; k4++) {
        float4 w = Wf4[vc * 64 + 32 + k4];
#pragma unroll
        for (int i = 0; i < 16; i++) {
            float4 cx = cs4[(2 * i + sg) * 32 + k4];
            acc2[i] = fmaf(w.x, cx.x, acc2[i]);
            acc2[i] = fmaf(w.y, cx.y, acc2[i]);
            acc2[i] = fmaf(w.z, cx.z, acc2[i]);
            acc2[i] = fmaf(w.w, cx.w, acc2[i]);
        }
    }
#pragma unroll
    for (int i = 0; i < 16; i++)
        logits[((size_t)b * Sn + s0 + 2 * i + sg) * Vv + vc] = acc2[i] + bb;
}

// ============================================================================
// launch
// ============================================================================
extern "C" void kernel_launch(void* const* d_in, const int* in_sizes, int n_in,
                              void* d_out, int out_size) {
    const int*   x   = (const int*)d_in[0];
    const float* emb = (const float*)d_in[1];
    const float* Wih = (const float*)d_in[2];
    const float* Whh = (const float*)d_in[3];
    const float* bih = (const float*)d_in[4];
    const float* bhh = (const float*)d_in[5];
    const float* Wq  = (const float*)d_in[6];
    const float* bq  = (const float*)d_in[7];
    const float* Wk  = (const float*)d_in[8];
    const float* bk  = (const float*)d_in[9];
    const float* v   = (const float*)d_in[10];
    const float* Wf  = (const float*)d_in[11];
    const float* bf  = (const float*)d_in[12];

    float* out    = (float*)d_out;
    float* logits = out;                               // (B,S,V) first

    const int LOGITS_N = Bn * Sn * Vv;                 // 262144
    float* hT;
    float* cT;
    if (out_size >= LOGITS_N + 2 * Bn * Hd) {
        hT = out + LOGITS_N;
        cT = hT + Bn * Hd;
    } else {
        float* dump = nullptr;
        cudaGetSymbolAddress((void**)&dump, g_state_dump);
        hT = dump;
        cT = dump + Bn * Hd;
    }

    cudaFuncSetAttribute(k_lstm, cudaFuncAttributeMaxDynamicSharedMemorySize, LSTM_SMEM);

    k_embed_xproj<<<128, 512>>>(x, emb, Wih, bih, bhh);
    k_lstm<<<Bn, 1024, LSTM_SMEM>>>(Whh, hT, cT);
    k_qk<<<128, 256>>>(Wq, bq, Wk, bk);
    k_scores<<<544, 256>>>(v);
    k_softmax<<<Bn * Sn, 256>>>();
    k_ctx_logits<<<64, 256>>>(Wf, bf, logits);
}

// round 5
// speedup vs baseline: 1.1836x; 1.1836x over previous
#include <cuda_runtime.h>
#include <math.h>

#define Bn 4
#define Sn 512
#define Hd 128
#define En 32     // embed_dim — E=32 (V,E,H = 128,32,128)
#define Vv 128
#define G4 512    // 4*H

typedef unsigned long long u64;

// ---------------- scratch (device globals: no allocation allowed) ----------------
__device__ float g_xproj[Bn*Sn*G4];   // 4 MB
__device__ float g_out[Bn*Sn*Hd];     // 1 MB
__device__ float g_q[Bn*Sn*Hd];       // 1 MB
__device__ float g_k[Bn*Sn*Hd];       // 1 MB
__device__ float g_scores[Bn*Sn*Sn];  // 4 MB (scores, then softmax weights in-place)
__device__ float g_state_dump[2*Bn*Hd]; // fallback if d_out has no room for hT/cT

// ---------------- helpers ----------------
__device__ __forceinline__ u64 fma2(u64 a, u64 b, u64 c) {
    u64 d;
    asm("fma.rn.f32x2 %0, %1, %2, %3;" : "=l"(d) : "l"(a), "l"(b), "l"(c));
    return d;
}
__device__ __forceinline__ u64 add2(u64 a, u64 b) {
    u64 d;
    asm("add.rn.f32x2 %0, %1, %2;" : "=l"(d) : "l"(a), "l"(b));
    return d;
}
// fast-but-accurate-enough activations (MUFU ex2/rcp; rel err ~1e-6)
__device__ __forceinline__ float sig_f(float x) {
    return __fdividef(1.0f, 1.0f + __expf(-x));
}
__device__ __forceinline__ float tanh_f(float x) {
    float e = __expf(-2.0f * x);
    return __fdividef(1.0f - e, 1.0f + e);
}
// hardware tanh approximation (rel err ~5e-4) — attention scores only
__device__ __forceinline__ float tanh_a(float x) {
    float y;
    asm("tanh.approx.f32 %0, %1;" : "=f"(y) : "f"(x));
    return y;
}

// ============================================================================
// Kernel 1: xproj[r, col] = dot(emb[x[r], :32], W_ih[col, :32]) + b_ih + b_hh
// ============================================================================
__global__ void k_embed_xproj(const int* __restrict__ x, const float* __restrict__ emb,
                              const float* __restrict__ Wih, const float* __restrict__ bih,
                              const float* __restrict__ bhh) {
    __shared__ __align__(16) float e_s[16 * En];
    int tid = threadIdx.x;                          // 512
    int r0 = blockIdx.x * 16;
    e_s[tid] = emb[x[r0 + (tid >> 5)] * En + (tid & 31)];
    __syncthreads();

    int col = tid;
    const float4* W4 = (const float4*)(Wih + col * En);
    float4 w[8];
#pragma unroll
    for (int i = 0; i < 8; i++) w[i] = W4[i];
    float bb = bih[col] + bhh[col];

#pragma unroll 4
    for (int r = 0; r < 16; r++) {
        const float4* e4 = (const float4*)(e_s + r * En);
        float a = bb;
#pragma unroll
        for (int i = 0; i < 8; i++) {
            float4 e = e4[i];
            a = fmaf(w[i].x, e.x, a);
            a = fmaf(w[i].y, e.y, a);
            a = fmaf(w[i].z, e.z, a);
            a = fmaf(w[i].w, e.w, a);
        }
        g_xproj[(size_t)(r0 + r) * G4 + col] = a;
    }
}

// ============================================================================
// Kernel 2: LSTM (packed f32x2, LDS.128 operand loads, fast gates).
// One block per batch, 1024 threads. Thread t: row j = t&511, half = t>>9.
// W_hh row-half: 40 floats in regs (20 u64 pairs), 24 floats in smem as
// ulonglong2 (6 groups). h read as ulonglong2 (LDS.128 broadcast).
// ============================================================================
#define RKP 20   // register k-pairs (40 floats)
#define SGRP 6   // smem ulonglong2 groups (24 floats)
#define LSTM_SMEM (2*SGRP*512*16 + 1024*4 + 128*4)

__global__ __launch_bounds__(1024, 1) void k_lstm(const float* __restrict__ Whh,
                                                  float* __restrict__ hT,
                                                  float* __restrict__ cT) {
    extern __shared__ __align__(16) char smraw[];
    ulonglong2* WS  = (ulonglong2*)smraw;                     // [2*SGRP*512]
    float* part = (float*)(smraw + (size_t)2*SGRP*512*16);    // [1024]
    float* h_s  = part + 1024;                                // [128]

    int tid  = threadIdx.x;
    int j    = tid & 511;
    int half = tid >> 9;
    int b    = blockIdx.x;

    // weights: row j, k in [half*64, half*64+64)
    const char* wrow = (const char*)(Whh + j * Hd + half * 64);
    u64 wreg[RKP];
#pragma unroll
    for (int q = 0; q < RKP / 2; q++) {
        ulonglong2 wv = ((const ulonglong2*)wrow)[q];
        wreg[2 * q]     = wv.x;
        wreg[2 * q + 1] = wv.y;
    }
#pragma unroll
    for (int g = 0; g < SGRP; g++)
        WS[(half * SGRP + g) * 512 + j] = ((const ulonglong2*)(wrow + 160))[g];
    if (tid < 128) h_s[tid] = 0.0f;
    float c = 0.0f, hlast = 0.0f;
    __syncthreads();

    const ulonglong2* h2v = (const ulonglong2*)h_s;   // 32 entries of 4 floats
    const float* xpb  = g_xproj + (size_t)b * Sn * G4;
    float*       outb = g_out   + (size_t)b * Sn * Hd;
    int hq = half * 16;                                // float4-index base of this half

    for (int t = 0; t < Sn; t++) {
        float xp0 = 0.f, xp1 = 0.f, xp2 = 0.f, xp3 = 0.f;
        if (tid < 128) {
            const float* xp = xpb + (size_t)t * G4;
            xp0 = xp[tid];       xp1 = xp[tid + 128];
            xp2 = xp[tid + 256]; xp3 = xp[tid + 384];
        }
        // phase A: partial dot of W_hh[j, half-range] with h
        u64 a0 = 0ull, a1 = 0ull, a2 = 0ull, a3 = 0ull;
#pragma unroll
        for (int q = 0; q < 10; q++) {
            ulonglong2 hv = h2v[hq + q];
            a0 = fma2(wreg[2 * q],     hv.x, a0);
            a1 = fma2(wreg[2 * q + 1], hv.y, a1);
        }
#pragma unroll
        for (int g = 0; g < SGRP; g++) {
            ulonglong2 wv = WS[(half * SGRP + g) * 512 + j];
            ulonglong2 hv = h2v[hq + 10 + g];
            a2 = fma2(wv.x, hv.x, a2);
            a3 = fma2(wv.y, hv.y, a3);
        }
        u64 ssum = add2(add2(a0, a1), add2(a2, a3));
        float2 sf = *(float2*)&ssum;
        part[tid] = sf.x + sf.y;
        __syncthreads();

        // phase B: gates + state update (threads 0..127), fast activations
        if (tid < 128) {
            float gi = xp0 + part[tid]       + part[512 + tid];
            float gf = xp1 + part[128 + tid] + part[640 + tid];
            float gg = xp2 + part[256 + tid] + part[768 + tid];
            float go = xp3 + part[384 + tid] + part[896 + tid];
            c = sig_f(gf) * c + sig_f(gi) * tanh_f(gg);
            float h = sig_f(go) * tanh_f(c);
            hlast = h;
            h_s[tid] = h;
            outb[(size_t)t * Hd + tid] = h;
        }
        __syncthreads();
    }
    if (tid < 128) {
        hT[b * Hd + tid] = hlast;
        cT[b * Hd + tid] = c;
    }
}

// ============================================================================
// Kernel 3: q = out @ Wqᵀ + bq ; k = out @ Wkᵀ + bk. 16 rows/block, 256 thr.
// ============================================================================
__global__ void k_qk(const float* __restrict__ Wq, const float* __restrict__ bq,
                     const float* __restrict__ Wk, const float* __restrict__ bk) {
    __shared__ __align__(16) float o_s[16 * 128];
    int tid = threadIdx.x;
    int r0 = blockIdx.x * 16;
    for (int i = tid; i < 2048; i += 256)
        o_s[i] = g_out[(size_t)r0 * Hd + i];
    __syncthreads();

    const float* W    = (tid < 128) ? Wq : Wk;
    const float* bias = (tid < 128) ? bq : bk;
    float*       dst  = (tid < 128) ? g_q : g_k;
    int c = tid & 127;

    const float4* W4  = (const float4*)W;
    const float4* os4 = (const float4*)o_s;
    float acc[16];
    float bb = bias[c];
#pragma unroll
    for (int r = 0; r < 16; r++) acc[r] = bb;
#pragma unroll 4
    for (int k4 = 0; k4 < 32; k4++) {
        float4 w = W4[c * 32 + k4];
#pragma unroll
        for (int r = 0; r < 16; r++) {
            float4 o = os4[r * 32 + k4];
            acc[r] = fmaf(w.x, o.x, acc[r]);
            acc[r] = fmaf(w.y, o.y, acc[r]);
            acc[r] = fmaf(w.z, o.z, acc[r]);
            acc[r] = fmaf(w.w, o.w, acc[r]);
        }
    }
#pragma unroll
    for (int r = 0; r < 16; r++)
        dst[(size_t)(r0 + r) * Hd + c] = acc[r];
}

// ============================================================================
// Kernel 4: scores via hardware tanh.approx (MUFU). 32x32 causal tiles.
// ============================================================================
__global__ void k_scores(const float* __restrict__ v) {
    __shared__ __align__(16) float q_s[32 * 128];
    __shared__ float kT[128 * 33];
    __shared__ float v_s[128];
    int tid = threadIdx.x;
    int b = blockIdx.x / 136;
    int r = blockIdx.x % 136;
    int si = 0;
    while (((si + 1) * (si + 2)) >> 1 <= r) si++;
    int ti = r - ((si * (si + 1)) >> 1);
    int s0 = si * 32, t0 = ti * 32;

    const float* qb = g_q + ((size_t)b * Sn + s0) * Hd;
    const float* kb = g_k + ((size_t)b * Sn + t0) * Hd;
    for (int i = tid; i < 4096; i += 256) q_s[i] = qb[i];
    for (int i = tid; i < 4096; i += 256) {
        int tt = i >> 7, h = i & 127;
        kT[h * 33 + tt] = kb[i];
    }
    if (tid < 128) v_s[tid] = v[tid];
    __syncthreads();

    int tl = tid & 31, sb = tid >> 5;
    float acc[4] = {0.f, 0.f, 0.f, 0.f};
#pragma unroll 2
    for (int h = 0; h < 128; h++) {
        float kv = kT[h * 33 + tl];
        float vv = v_s[h];
#pragma unroll
        for (int p = 0; p < 4; p++)
            acc[p] = fmaf(vv, tanh_a(q_s[(sb + (p << 3)) * 128 + h] + kv), acc[p]);
    }
    int t = t0 + tl;
#pragma unroll
    for (int p = 0; p < 4; p++) {
        int s = s0 + sb + (p << 3);
        if (t <= s)
            g_scores[((size_t)b * Sn + s) * Sn + t] = acc[p];
    }
}

// ============================================================================
// Kernel 5: causal softmax per (b,s) row, zero-fills masked entries.
// ============================================================================
__global__ void k_softmax() {
    __shared__ float red[256];
    int tid = threadIdx.x;
    int row = blockIdx.x;
    int s = row & (Sn - 1);
    float* sc = g_scores + (size_t)row * Sn;
    int n = s + 1;

    float x0 = (tid < n) ? sc[tid] : -1e30f;
    float x1 = (tid + 256 < n) ? sc[tid + 256] : -1e30f;
    red[tid] = fmaxf(x0, x1);
    __syncthreads();
    for (int o = 128; o > 0; o >>= 1) {
        if (tid < o) red[tid] = fmaxf(red[tid], red[tid + o]);
        __syncthreads();
    }
    float m = red[0];
    __syncthreads();

    float e0 = (tid < n) ? __expf(x0 - m) : 0.0f;
    float e1 = (tid + 256 < n) ? __expf(x1 - m) : 0.0f;
    red[tid] = e0 + e1;
    __syncthreads();
    for (int o = 128; o > 0; o >>= 1) {
        if (tid < o) red[tid] += red[tid + o];
        __syncthreads();
    }
    float inv = __fdividef(1.0f, red[0]);
    sc[tid]       = e0 * inv;
    sc[tid + 256] = e1 * inv;
}

// ============================================================================
// Kernel 6: ctx then logits = [out, ctx] @ Wfᵀ + bf. 32 s-rows/block.
// ============================================================================
__global__ void k_ctx_logits(const float* __restrict__ Wf, const float* __restrict__ bf,
                             float* __restrict__ logits) {
    __shared__ float w_s[32 * 32];
    __shared__ __align__(16) float ctx_s[32 * 128];
    __shared__ __align__(16) float out_s[32 * 128];
    int tid = threadIdx.x;
    int b  = blockIdx.x >> 4;
    int s0 = (blockIdx.x & 15) << 5;

    for (int i = tid; i < 4096; i += 256)
        out_s[i] = g_out[((size_t)b * Sn + s0) * Hd + i];

    int h = tid & 127, sg = tid >> 7;
    float acc[16];
#pragma unroll
    for (int i = 0; i < 16; i++) acc[i] = 0.0f;

    int tend = s0 + 32;
    for (int tc0 = 0; tc0 < tend; tc0 += 32) {
        __syncthreads();
        for (int i = tid; i < 1024; i += 256) {
            int sl = i >> 5, tc = i & 31;
            w_s[i] = g_scores[((size_t)b * Sn + s0 + sl) * Sn + tc0 + tc];
        }
        __syncthreads();
#pragma unroll 4
        for (int tc = 0; tc < 32; tc++) {
            float ov = g_out[((size_t)b * Sn + tc0 + tc) * Hd + h];
#pragma unroll
            for (int i = 0; i < 16; i++)
                acc[i] = fmaf(w_s[(2 * i + sg) * 32 + tc], ov, acc[i]);
        }
    }
    __syncthreads();
#pragma unroll
    for (int i = 0; i < 16; i++) ctx_s[(2 * i + sg) * 128 + h] = acc[i];
    __syncthreads();

    int vc = tid & 127;
    float bb = bf[vc];
    const float4* Wf4 = (const float4*)Wf;
    const float4* os4 = (const float4*)out_s;
    const float4* cs4 = (const float4*)ctx_s;
    float acc2[16];
#pragma unroll
    for (int i = 0; i < 16; i++) acc2[i] = 0.0f;
#pragma unroll 2
    for (int k4 = 0; k4 < 32; k4++) {
        float4 w = Wf4[vc * 64 + k4];
#pragma unroll
        for (int i = 0; i < 16; i++) {
            float4 o = os4[(2 * i + sg) * 32 + k4];
            acc2[i] = fmaf(w.x, o.x, acc2[i]);
            acc2[i] = fmaf(w.y, o.y, acc2[i]);
            acc2[i] = fmaf(w.z, o.z, acc2[i]);
            acc2[i] = fmaf(w.w, o.w, acc2[i]);
        }
    }
#pragma unroll 2
    for (int k4 = 0; k4 < 32; k4++) {
        float4 w = Wf4[vc * 64 + 32 + k4];
#pragma unroll
        for (int i = 0; i < 16; i++) {
            float4 cx = cs4[(2 * i + sg) * 32 + k4];
            acc2[i] = fmaf(w.x, cx.x, acc2[i]);
            acc2[i] = fmaf(w.y, cx.y, acc2[i]);
            acc2[i] = fmaf(w.z, cx.z, acc2[i]);
            acc2[i] = fmaf(w.w, cx.w, acc2[i]);
        }
    }
#pragma unroll
    for (int i = 0; i < 16; i++)
        logits[((size_t)b * Sn + s0 + 2 * i + sg) * Vv + vc] = acc2[i] + bb;
}

// ============================================================================
// launch
// ============================================================================
extern "C" void kernel_launch(void* const* d_in, const int* in_sizes, int n_in,
                              void* d_out, int out_size) {
    const int*   x   = (const int*)d_in[0];
    const float* emb = (const float*)d_in[1];
    const float* Wih = (const float*)d_in[2];
    const float* Whh = (const float*)d_in[3];
    const float* bih = (const float*)d_in[4];
    const float* bhh = (const float*)d_in[5];
    const float* Wq  = (const float*)d_in[6];
    const float* bq  = (const float*)d_in[7];
    const float* Wk  = (const float*)d_in[8];
    const float* bk  = (const float*)d_in[9];
    const float* v   = (const float*)d_in[10];
    const float* Wf  = (const float*)d_in[11];
    const float* bf  = (const float*)d_in[12];

    float* out    = (float*)d_out;
    float* logits = out;

    const int LOGITS_N = Bn * Sn * Vv;
    float* hT;
    float* cT;
    if (out_size >= LOGITS_N + 2 * Bn * Hd) {
        hT = out + LOGITS_N;
        cT = hT + Bn * Hd;
    } else {
        float* dump = nullptr;
        cudaGetSymbolAddress((void**)&dump, g_state_dump);
        hT = dump;
        cT = dump + Bn * Hd;
    }

    cudaFuncSetAttribute(k_lstm, cudaFuncAttributeMaxDynamicSharedMemorySize, LSTM_SMEM);

    k_embed_xproj<<<128, 512>>>(x, emb, Wih, bih, bhh);
    k_lstm<<<Bn, 1024, LSTM_SMEM>>>(Whh, hT, cT);
    k_qk<<<128, 256>>>(Wq, bq, Wk, bk);
    k_scores<<<544, 256>>>(v);
    k_softmax<<<Bn * Sn, 256>>>();
    k_ctx_logits<<<64, 256>>>(Wf, bf, logits);
}

// round 6
// speedup vs baseline: 1.4444x; 1.2203x over previous
#include <cuda_runtime.h>
#include <math.h>

#define Bn 4
#define Sn 512
#define Hd 128
#define En 32     // embed_dim — E=32 (V,E,H = 128,32,128)
#define Vv 128
#define G4 512    // 4*H

typedef unsigned long long u64;

// ---------------- scratch (device globals: no allocation allowed) ----------------
__device__ float g_xproj[Bn*Sn*G4];   // 4 MB
__device__ float g_out[Bn*Sn*Hd];     // 1 MB
__device__ float g_q[Bn*Sn*Hd];       // 1 MB
__device__ float g_k[Bn*Sn*Hd];       // 1 MB
__device__ float g_scores[Bn*Sn*Sn];  // 4 MB
__device__ float g_state_dump[2*Bn*Hd];

// ---------------- helpers ----------------
__device__ __forceinline__ u64 fma2(u64 a, u64 b, u64 c) {
    u64 d;
    asm("fma.rn.f32x2 %0, %1, %2, %3;" : "=l"(d) : "l"(a), "l"(b), "l"(c));
    return d;
}
__device__ __forceinline__ u64 add2(u64 a, u64 b) {
    u64 d;
    asm("add.rn.f32x2 %0, %1, %2;" : "=l"(d) : "l"(a), "l"(b));
    return d;
}
__device__ __forceinline__ float sig_f(float x) {
    return __fdividef(1.0f, 1.0f + __expf(-x));
}
__device__ __forceinline__ float tanh_f(float x) {
    float e = __expf(-2.0f * x);
    return __fdividef(1.0f - e, 1.0f + e);
}
__device__ __forceinline__ float tanh_a(float x) {
    float y;
    asm("tanh.approx.f32 %0, %1;" : "=f"(y) : "f"(x));
    return y;
}

// ============================================================================
// Kernel 1: xproj[r, col] = dot(emb[x[r], :32], W_ih[col, :32]) + b_ih + b_hh
// ============================================================================
__global__ void k_embed_xproj(const int* __restrict__ x, const float* __restrict__ emb,
                              const float* __restrict__ Wih, const float* __restrict__ bih,
                              const float* __restrict__ bhh) {
    __shared__ __align__(16) float e_s[16 * En];
    int tid = threadIdx.x;                          // 512
    int r0 = blockIdx.x * 16;
    e_s[tid] = emb[x[r0 + (tid >> 5)] * En + (tid & 31)];
    __syncthreads();

    int col = tid;
    const float4* W4 = (const float4*)(Wih + col * En);
    float4 w[8];
#pragma unroll
    for (int i = 0; i < 8; i++) w[i] = W4[i];
    float bb = bih[col] + bhh[col];

#pragma unroll 4
    for (int r = 0; r < 16; r++) {
        const float4* e4 = (const float4*)(e_s + r * En);
        float a = bb;
#pragma unroll
        for (int i = 0; i < 8; i++) {
            float4 e = e4[i];
            a = fmaf(w[i].x, e.x, a);
            a = fmaf(w[i].y, e.y, a);
            a = fmaf(w[i].z, e.z, a);
            a = fmaf(w[i].w, e.w, a);
        }
        g_xproj[(size_t)(r0 + r) * G4 + col] = a;
    }
}

// ============================================================================
// Kernel 2: LSTM. One block per batch, 512 threads (128-reg budget, NO SPILLS).
// Thread j owns FULL gate row j: 80 weight floats in regs (40 u64 pairs),
// 48 floats in smem (12 ulonglong2 groups, conflict-free). Packed f32x2 FMA.
// No cross-thread dot reduction — dots[j] written whole, one barrier.
// ============================================================================
#define RP  40   // register k-pairs (80 floats)
#define SG  12   // smem ulonglong2 groups (48 floats)
#define LSTM_SMEM (SG*512*16 + 512*4 + 128*4)

__global__ __launch_bounds__(512, 1) void k_lstm(const float* __restrict__ Whh,
                                                 float* __restrict__ hT,
                                                 float* __restrict__ cT) {
    extern __shared__ __align__(16) char smraw[];
    ulonglong2* WS = (ulonglong2*)smraw;                    // [SG*512]
    float* dots = (float*)(smraw + (size_t)SG * 512 * 16);  // [512]
    float* h_s  = dots + 512;                               // [128]

    int j = threadIdx.x;
    int b = blockIdx.x;

    // weights: row j. floats [0,80) -> regs as u64 pairs; [80,128) -> smem.
    const float* wrow = Whh + j * Hd;
    u64 wreg[RP];
#pragma unroll
    for (int q = 0; q < RP / 2; q++) {
        ulonglong2 wv = ((const ulonglong2*)wrow)[q];       // row 512B-aligned
        wreg[2 * q]     = wv.x;
        wreg[2 * q + 1] = wv.y;
    }
#pragma unroll
    for (int g = 0; g < SG; g++)
        WS[g * 512 + j] = ((const ulonglong2*)(wrow + 80))[g];  // +320B, 16B-aligned
    if (j < 128) h_s[j] = 0.0f;
    float c = 0.0f, hlast = 0.0f;
    __syncthreads();

    const ulonglong2* h2v = (const ulonglong2*)h_s;   // 32 groups of 4 floats
    const float* xpb  = g_xproj + (size_t)b * Sn * G4;
    float*       outb = g_out   + (size_t)b * Sn * Hd;

    for (int t = 0; t < Sn; t++) {
        float xp0 = 0.f, xp1 = 0.f, xp2 = 0.f, xp3 = 0.f;
        if (j < 128) {
            const float* xp = xpb + (size_t)t * G4;
            xp0 = xp[j];       xp1 = xp[j + 128];
            xp2 = xp[j + 256]; xp3 = xp[j + 384];
        }
        // phase A: full-row dot. h loads are warp-broadcast LDS.128.
        u64 a0 = 0ull, a1 = 0ull, a2 = 0ull, a3 = 0ull;
#pragma unroll
        for (int q = 0; q < 20; q++) {
            ulonglong2 hv = h2v[q];
            a0 = fma2(wreg[2 * q],     hv.x, a0);
            a1 = fma2(wreg[2 * q + 1], hv.y, a1);
        }
#pragma unroll
        for (int g = 0; g < SG; g++) {
            ulonglong2 wv = WS[g * 512 + j];
            ulonglong2 hv = h2v[20 + g];
            a2 = fma2(wv.x, hv.x, a2);
            a3 = fma2(wv.y, hv.y, a3);
        }
        u64 ssum = add2(add2(a0, a1), add2(a2, a3));
        float2 sf = *(float2*)&ssum;
        dots[j] = sf.x + sf.y;
        __syncthreads();

        // phase B: gates + state update (threads 0..127)
        if (j < 128) {
            float gi = xp0 + dots[j];
            float gf = xp1 + dots[j + 128];
            float gg = xp2 + dots[j + 256];
            float go = xp3 + dots[j + 384];
            c = sig_f(gf) * c + sig_f(gi) * tanh_f(gg);
            float h = sig_f(go) * tanh_f(c);
            hlast = h;
            h_s[j] = h;
            outb[(size_t)t * Hd + j] = h;
        }
        __syncthreads();
    }
    if (j < 128) {
        hT[b * Hd + j] = hlast;
        cT[b * Hd + j] = c;
    }
}

// ============================================================================
// Kernel 3: q = out @ Wqᵀ + bq ; k = out @ Wkᵀ + bk. 16 rows/block, 256 thr.
// ============================================================================
__global__ void k_qk(const float* __restrict__ Wq, const float* __restrict__ bq,
                     const float* __restrict__ Wk, const float* __restrict__ bk) {
    __shared__ __align__(16) float o_s[16 * 128];
    int tid = threadIdx.x;
    int r0 = blockIdx.x * 16;
    for (int i = tid; i < 2048; i += 256)
        o_s[i] = g_out[(size_t)r0 * Hd + i];
    __syncthreads();

    const float* W    = (tid < 128) ? Wq : Wk;
    const float* bias = (tid < 128) ? bq : bk;
    float*       dst  = (tid < 128) ? g_q : g_k;
    int c = tid & 127;

    const float4* W4  = (const float4*)W;
    const float4* os4 = (const float4*)o_s;
    float acc[16];
    float bb = bias[c];
#pragma unroll
    for (int r = 0; r < 16; r++) acc[r] = bb;
#pragma unroll 4
    for (int k4 = 0; k4 < 32; k4++) {
        float4 w = W4[c * 32 + k4];
#pragma unroll
        for (int r = 0; r < 16; r++) {
            float4 o = os4[r * 32 + k4];
            acc[r] = fmaf(w.x, o.x, acc[r]);
            acc[r] = fmaf(w.y, o.y, acc[r]);
            acc[r] = fmaf(w.z, o.z, acc[r]);
            acc[r] = fmaf(w.w, o.w, acc[r]);
        }
    }
#pragma unroll
    for (int r = 0; r < 16; r++)
        dst[(size_t)(r0 + r) * Hd + c] = acc[r];
}

// ============================================================================
// Kernel 4: scores via hardware tanh.approx (MUFU). 32x32 causal tiles.
// ============================================================================
__global__ void k_scores(const float* __restrict__ v) {
    __shared__ __align__(16) float q_s[32 * 128];
    __shared__ float kT[128 * 33];
    __shared__ float v_s[128];
    int tid = threadIdx.x;
    int b = blockIdx.x / 136;
    int r = blockIdx.x % 136;
    int si = 0;
    while (((si + 1) * (si + 2)) >> 1 <= r) si++;
    int ti = r - ((si * (si + 1)) >> 1);
    int s0 = si * 32, t0 = ti * 32;

    const float* qb = g_q + ((size_t)b * Sn + s0) * Hd;
    const float* kb = g_k + ((size_t)b * Sn + t0) * Hd;
    for (int i = tid; i < 4096; i += 256) q_s[i] = qb[i];
    for (int i = tid; i < 4096; i += 256) {
        int tt = i >> 7, h = i & 127;
        kT[h * 33 + tt] = kb[i];
    }
    if (tid < 128) v_s[tid] = v[tid];
    __syncthreads();

    int tl = tid & 31, sb = tid >> 5;
    float acc[4] = {0.f, 0.f, 0.f, 0.f};
#pragma unroll 2
    for (int h = 0; h < 128; h++) {
        float kv = kT[h * 33 + tl];
        float vv = v_s[h];
#pragma unroll
        for (int p = 0; p < 4; p++)
            acc[p] = fmaf(vv, tanh_a(q_s[(sb + (p << 3)) * 128 + h] + kv), acc[p]);
    }
    int t = t0 + tl;
#pragma unroll
    for (int p = 0; p < 4; p++) {
        int s = s0 + sb + (p << 3);
        if (t <= s)
            g_scores[((size_t)b * Sn + s) * Sn + t] = acc[p];
    }
}

// ============================================================================
// Kernel 5: causal softmax per (b,s) row, zero-fills masked entries.
// ============================================================================
__global__ void k_softmax() {
    __shared__ float red[256];
    int tid = threadIdx.x;
    int row = blockIdx.x;
    int s = row & (Sn - 1);
    float* sc = g_scores + (size_t)row * Sn;
    int n = s + 1;

    float x0 = (tid < n) ? sc[tid] : -1e30f;
    float x1 = (tid + 256 < n) ? sc[tid + 256] : -1e30f;
    red[tid] = fmaxf(x0, x1);
    __syncthreads();
    for (int o = 128; o > 0; o >>= 1) {
        if (tid < o) red[tid] = fmaxf(red[tid], red[tid + o]);
        __syncthreads();
    }
    float m = red[0];
    __syncthreads();

    float e0 = (tid < n) ? __expf(x0 - m) : 0.0f;
    float e1 = (tid + 256 < n) ? __expf(x1 - m) : 0.0f;
    red[tid] = e0 + e1;
    __syncthreads();
    for (int o = 128; o > 0; o >>= 1) {
        if (tid < o) red[tid] += red[tid + o];
        __syncthreads();
    }
    float inv = __fdividef(1.0f, red[0]);
    sc[tid]       = e0 * inv;
    sc[tid + 256] = e1 * inv;
}

// ============================================================================
// Kernel 6: ctx then logits = [out, ctx] @ Wfᵀ + bf. 32 s-rows/block.
// ============================================================================
__global__ void k_ctx_logits(const float* __restrict__ Wf, const float* __restrict__ bf,
                             float* __restrict__ logits) {
    __shared__ float w_s[32 * 32];
    __shared__ __align__(16) float ctx_s[32 * 128];
    __shared__ __align__(16) float out_s[32 * 128];
    int tid = threadIdx.x;
    int b  = blockIdx.x >> 4;
    int s0 = (blockIdx.x & 15) << 5;

    for (int i = tid; i < 4096; i += 256)
        out_s[i] = g_out[((size_t)b * Sn + s0) * Hd + i];

    int h = tid & 127, sg = tid >> 7;
    float acc[16];
#pragma unroll
    for (int i = 0; i < 16; i++) acc[i] = 0.0f;

    int tend = s0 + 32;
    for (int tc0 = 0; tc0 < tend; tc0 += 32) {
        __syncthreads();
        for (int i = tid; i < 1024; i += 256) {
            int sl = i >> 5, tc = i & 31;
            w_s[i] = g_scores[((size_t)b * Sn + s0 + sl) * Sn + tc0 + tc];
        }
        __syncthreads();
#pragma unroll 4
        for (int tc = 0; tc < 32; tc++) {
            float ov = g_out[((size_t)b * Sn + tc0 + tc) * Hd + h];
#pragma unroll
            for (int i = 0; i < 16; i++)
                acc[i] = fmaf(w_s[(2 * i + sg) * 32 + tc], ov, acc[i]);
        }
    }
    __syncthreads();
#pragma unroll
    for (int i = 0; i < 16; i++) ctx_s[(2 * i + sg) * 128 + h] = acc[i];
    __syncthreads();

    int vc = tid & 127;
    float bb = bf[vc];
    const float4* Wf4 = (const float4*)Wf;
    const float4* os4 = (const float4*)out_s;
    const float4* cs4 = (const float4*)ctx_s;
    float acc2[16];
#pragma unroll
    for (int i = 0; i < 16; i++) acc2[i] = 0.0f;
#pragma unroll 2
    for (int k4 = 0; k4 < 32; k4++) {
        float4 w = Wf4[vc * 64 + k4];
#pragma unroll
        for (int i = 0; i < 16; i++) {
            float4 o = os4[(2 * i + sg) * 32 + k4];
            acc2[i] = fmaf(w.x, o.x, acc2[i]);
            acc2[i] = fmaf(w.y, o.y, acc2[i]);
            acc2[i] = fmaf(w.z, o.z, acc2[i]);
            acc2[i] = fmaf(w.w, o.w, acc2[i]);
        }
    }
#pragma unroll 2
    for (int k4 = 0; k4 < 32; k4++) {
        float4 w = Wf4[vc * 64 + 32 + k4];
#pragma unroll
        for (int i = 0; i < 16; i++) {
            float4 cx = cs4[(2 * i + sg) * 32 + k4];
            acc2[i] = fmaf(w.x, cx.x, acc2[i]);
            acc2[i] = fmaf(w.y, cx.y, acc2[i]);
            acc2[i] = fmaf(w.z, cx.z, acc2[i]);
            acc2[i] = fmaf(w.w, cx.w, acc2[i]);
        }
    }
#pragma unroll
    for (int i = 0; i < 16; i++)
        logits[((size_t)b * Sn + s0 + 2 * i + sg) * Vv + vc] = acc2[i] + bb;
}

// ============================================================================
// launch
// ============================================================================
extern "C" void kernel_launch(void* const* d_in, const int* in_sizes, int n_in,
                              void* d_out, int out_size) {
    const int*   x   = (const int*)d_in[0];
    const float* emb = (const float*)d_in[1];
    const float* Wih = (const float*)d_in[2];
    const float* Whh = (const float*)d_in[3];
    const float* bih = (const float*)d_in[4];
    const float* bhh = (const float*)d_in[5];
    const float* Wq  = (const float*)d_in[6];
    const float* bq  = (const float*)d_in[7];
    const float* Wk  = (const float*)d_in[8];
    const float* bk  = (const float*)d_in[9];
    const float* v   = (const float*)d_in[10];
    const float* Wf  = (const float*)d_in[11];
    const float* bf  = (const float*)d_in[12];

    float* out    = (float*)d_out;
    float* logits = out;

    const int LOGITS_N = Bn * Sn * Vv;
    float* hT;
    float* cT;
    if (out_size >= LOGITS_N + 2 * Bn * Hd) {
        hT = out + LOGITS_N;
        cT = hT + Bn * Hd;
    } else {
        float* dump = nullptr;
        cudaGetSymbolAddress((void**)&dump, g_state_dump);
        hT = dump;
        cT = dump + Bn * Hd;
    }

    cudaFuncSetAttribute(k_lstm, cudaFuncAttributeMaxDynamicSharedMemorySize, LSTM_SMEM);

    k_embed_xproj<<<128, 512>>>(x, emb, Wih, bih, bhh);
    k_lstm<<<Bn, 512, LSTM_SMEM>>>(Whh, hT, cT);
    k_qk<<<128, 256>>>(Wq, bq, Wk, bk);
    k_scores<<<544, 256>>>(v);
    k_softmax<<<Bn * Sn, 256>>>();
    k_ctx_logits<<<64, 256>>>(Wf, bf, logits);
}